// round 3
// baseline (speedup 1.0000x reference)
#include <cuda_runtime.h>
#include <math.h>

typedef unsigned long long u64;

#define MSG_DIM 100
#define MEM_DIM 172
#define KDIM    272          // MSG_DIM + MEM_DIM
#define JPAD    176          // MEM_DIM padded to warp-friendly
#define ROWS    20           // update rows per gru block
#define NTHREADS 192
#define XS      20           // xT row stride (floats) == ROWS, 80B (16B aligned)
#define NCH     68           // KDIM / 4 chunks
#define NCH1    25           // chunks in phase 1 (k < 100)
#define ILV     10           // copy-block interleave
#define MASK_CAP (4u << 20)

// ---------------------------------------------------------------------------
// Persistent scratch
// ---------------------------------------------------------------------------
__device__ float4 g_W4 [KDIM * JPAD];    // {wr, wz, wn, 0} K-major
__device__ float  g_bias[4 * JPAD];
__device__ unsigned char g_mask[MASK_CAP];

// ---- packed fp32x2 helpers ------------------------------------------------
__device__ __forceinline__ u64 fma2(u64 b, u64 x, u64 c) {
    u64 d;
    asm("fma.rn.f32x2 %0, %1, %2, %3;" : "=l"(d) : "l"(b), "l"(x), "l"(c));
    return d;
}
__device__ __forceinline__ u64 dup2(float v) {
    u64 d; unsigned u = __float_as_uint(v);
    asm("mov.b64 %0, {%1, %1};" : "=l"(d) : "r"(u));
    return d;
}
__device__ __forceinline__ float2 unpack2(u64 d) {
    unsigned lo, hi;
    asm("mov.b64 {%0, %1}, %2;" : "=r"(lo), "=r"(hi) : "l"(d));
    return make_float2(__uint_as_float(lo), __uint_as_float(hi));
}

// ---------------------------------------------------------------------------
// Prep: pack weights {wr, wz, wn, 0} K-major + combined bias.
// ---------------------------------------------------------------------------
__global__ void prep_kernel(const float* __restrict__ W_ih,
                            const float* __restrict__ W_hh,
                            const float* __restrict__ b_ih,
                            const float* __restrict__ b_hh) {
    int idx = blockIdx.x * blockDim.x + threadIdx.x;
    if (idx < KDIM * JPAD) {
        int k = idx / JPAD;
        int j = idx - k * JPAD;
        float wr = 0.f, wz = 0.f, wn = 0.f;
        if (j < MEM_DIM) {
            if (k < MSG_DIM) {
                wr = W_ih[j * MSG_DIM + k];
                wz = W_ih[(MEM_DIM + j) * MSG_DIM + k];
                wn = W_ih[(2 * MEM_DIM + j) * MSG_DIM + k];
            } else {
                int kk = k - MSG_DIM;
                wr = W_hh[j * MEM_DIM + kk];
                wz = W_hh[(MEM_DIM + j) * MEM_DIM + kk];
                wn = W_hh[(2 * MEM_DIM + j) * MEM_DIM + kk];
            }
        }
        g_W4[idx] = make_float4(wr, wz, wn, 0.f);
    }
    if (idx < JPAD) {
        int j = idx;
        float br = 0.f, bz = 0.f, bi = 0.f, bh = 0.f;
        if (j < MEM_DIM) {
            br = b_ih[j]               + b_hh[j];
            bz = b_ih[MEM_DIM + j]     + b_hh[MEM_DIM + j];
            bi = b_ih[2 * MEM_DIM + j];
            bh = b_hh[2 * MEM_DIM + j];
        }
        g_bias[j]            = br;
        g_bias[JPAD + j]     = bz;
        g_bias[2 * JPAD + j] = bi;
        g_bias[3 * JPAD + j] = bh;
    }
}

__global__ void mask_kernel(const int* __restrict__ node_ids, int n_upd) {
    int i = blockIdx.x * blockDim.x + threadIdx.x;
    if (i < n_upd) {
        int nid = node_ids[i];
        if (nid >= 0 && (unsigned)nid < MASK_CAP) g_mask[nid] = 1;
    }
}

// Fallback plain copy
__global__ void copy_kernel(const float* __restrict__ src, float* __restrict__ dst, long long n) {
    long long i = (long long)blockIdx.x * blockDim.x + threadIdx.x;
    long long n4 = n >> 2;
    if (i < n4) ((float4*)dst)[i] = ((const float4*)src)[i];
    long long tail = n & 3;
    if (i < tail) dst[n4 * 4 + i] = src[n4 * 4 + i];
}

// ---------------------------------------------------------------------------
// GRU inner machinery
// ---------------------------------------------------------------------------
__device__ __forceinline__ void kstep(const float4 w, const float* __restrict__ xrow,
                                      u64* __restrict__ ar, u64* __restrict__ az,
                                      u64* __restrict__ an) {
    u64 wr2 = dup2(w.x), wz2 = dup2(w.y), wn2 = dup2(w.z);
    const ulonglong2* __restrict__ xq = (const ulonglong2*)xrow;
    #pragma unroll
    for (int q = 0; q < ROWS / 4; q++) {
        ulonglong2 xv = xq[q];
        ar[2*q]   = fma2(wr2, xv.x, ar[2*q]);
        ar[2*q+1] = fma2(wr2, xv.y, ar[2*q+1]);
        az[2*q]   = fma2(wz2, xv.x, az[2*q]);
        az[2*q+1] = fma2(wz2, xv.y, az[2*q+1]);
        an[2*q]   = fma2(wn2, xv.x, an[2*q]);
        an[2*q+1] = fma2(wn2, xv.y, an[2*q+1]);
    }
}

__device__ __forceinline__ void chunk4(float4 (&wb)[4], const float4* __restrict__ pw,
                                       int kbase, int pref_k, bool do_pref,
                                       const float (*__restrict__ xT)[XS],
                                       u64* __restrict__ ar, u64* __restrict__ az,
                                       u64* __restrict__ an) {
    float4 w0 = wb[0], w1 = wb[1], w2 = wb[2], w3 = wb[3];
    if (do_pref) {
        wb[0] = __ldg(pw + (pref_k + 0) * JPAD);
        wb[1] = __ldg(pw + (pref_k + 1) * JPAD);
        wb[2] = __ldg(pw + (pref_k + 2) * JPAD);
        wb[3] = __ldg(pw + (pref_k + 3) * JPAD);
    }
    kstep(w0, xT[kbase + 0], ar, az, an);
    kstep(w1, xT[kbase + 1], ar, az, an);
    kstep(w2, xT[kbase + 2], ar, az, an);
    kstep(w3, xT[kbase + 3], ar, az, an);
}

// ---------------------------------------------------------------------------
// Fused kernel: sparse copy CTAs (bid % ILV == 0) + GRU CTAs.
// ---------------------------------------------------------------------------
__global__ void __launch_bounds__(NTHREADS, 2)
fused_kernel(const int*   __restrict__ node_ids,
             const float* __restrict__ messages,
             const float* __restrict__ timestamps,
             const float* __restrict__ memory,
             const float* __restrict__ last_update,
             float*       __restrict__ out,
             int n_upd, long long n_nodes, int copy_blocks)
{
    const int tid = threadIdx.x;
    const int bid = blockIdx.x;
    const long long nmem = n_nodes * (long long)MEM_DIM;

    // ---------------- copy role ----------------
    if ((bid % ILV == 0) && (bid / ILV < copy_blocks)) {
        const unsigned cid = bid / ILV;
        const unsigned stride = (unsigned)copy_blocks * NTHREADS;
        const unsigned n4 = (unsigned)(nmem >> 2);          // fits 32-bit (<=2^31)
        const float4* __restrict__ src = (const float4*)memory;
        float4* __restrict__ dst = (float4*)out;
        for (unsigned i = cid * NTHREADS + tid; i < n4; i += stride) {
            unsigned row = i / (MEM_DIM / 4);
            if (!g_mask[row]) dst[i] = src[i];
        }
        float* __restrict__ lo = out + nmem;
        const unsigned nn = (unsigned)n_nodes;
        for (unsigned i = cid * NTHREADS + tid; i < nn; i += stride) {
            if (!g_mask[i]) lo[i] = last_update[i];
        }
        return;
    }

    // ---------------- gru role ----------------
    int before = bid / ILV + 1;
    if (before > copy_blocks) before = copy_blocks;
    const int gid  = bid - before;
    const int row0 = gid * ROWS;
    if (row0 >= n_upd) return;

    __shared__ __align__(16) float xT[KDIM][XS];   // transposed [k][row]
    __shared__ int   s_nid[ROWS];
    __shared__ float s_ts [ROWS];

    if (tid < ROWS) {
        int r = row0 + tid;
        if (r < n_upd) { s_nid[tid] = node_ids[r]; s_ts[tid] = timestamps[r]; }
        else           { s_nid[tid] = -1;          s_ts[tid] = 0.f; }
    }
    __syncthreads();

    for (int idx = tid; idx < ROWS * KDIM; idx += NTHREADS) {
        int r = idx / KDIM;
        int k = idx - r * KDIM;
        float v = 0.f;
        int nid = s_nid[r];
        if (nid >= 0) {
            v = (k < MSG_DIM)
              ? messages[(size_t)(row0 + r) * MSG_DIM + k]
              : memory  [(size_t)nid * MEM_DIM + (k - MSG_DIM)];
        }
        xT[k][r] = v;
    }
    __syncthreads();

    const int j = tid;
    if (j < JPAD) {
        u64 ar[ROWS/2], az[ROWS/2], ani[ROWS/2], anh[ROWS/2];
        const u64 z0 = dup2(0.f);
        #pragma unroll
        for (int p = 0; p < ROWS/2; p++) { ar[p] = z0; az[p] = z0; ani[p] = z0; anh[p] = z0; }

        const float4* __restrict__ pw = g_W4 + j;
        float4 wb0[4], wb1[4];
        #pragma unroll
        for (int i = 0; i < 4; i++) {
            wb0[i] = __ldg(pw + (0 + i) * JPAD);
            wb1[i] = __ldg(pw + (4 + i) * JPAD);
        }

        // Phase 1: chunks 0..24 (k 0..99) -> n-accum = ani
        int c = 0;
        #pragma unroll 1
        for (; c + 1 < NCH1; c += 2) {
            chunk4(wb0, pw,  c      * 4, (c + 2) * 4, true, xT, ar, az, ani);
            chunk4(wb1, pw, (c + 1) * 4, (c + 3) * 4, true, xT, ar, az, ani);
        }
        // chunk 24 (parity 0): k 96..99, prefetch chunk 26
        chunk4(wb0, pw, 96, 104, true, xT, ar, az, ani);
        // Phase 2: chunk 25 (parity 1): k 100..103, prefetch chunk 27
        chunk4(wb1, pw, 100, 108, true, xT, ar, az, anh);
        #pragma unroll 1
        for (c = 26; c + 1 < NCH; c += 2) {
            chunk4(wb0, pw,  c      * 4, (c + 2) * 4, (c + 2) < NCH, xT, ar, az, anh);
            chunk4(wb1, pw, (c + 1) * 4, (c + 3) * 4, (c + 3) < NCH, xT, ar, az, anh);
        }

        if (j < MEM_DIM) {
            const float br = g_bias[j];
            const float bz = g_bias[JPAD + j];
            const float bi = g_bias[2 * JPAD + j];
            const float bh = g_bias[3 * JPAD + j];

            #pragma unroll
            for (int p = 0; p < ROWS/2; p++) {
                float2 arv = unpack2(ar [p]);
                float2 azv = unpack2(az [p]);
                float2 aiv = unpack2(ani[p]);
                float2 ahv = unpack2(anh[p]);
                #pragma unroll
                for (int s = 0; s < 2; s++) {
                    int r = 2 * p + s;
                    int nid = s_nid[r];
                    if (nid < 0) continue;
                    float a_r = (s ? arv.y : arv.x) + br;
                    float a_z = (s ? azv.y : azv.x) + bz;
                    float a_i = (s ? aiv.y : aiv.x) + bi;
                    float a_h = (s ? ahv.y : ahv.x) + bh;
                    float rg = 1.f / (1.f + expf(-a_r));
                    float zg = 1.f / (1.f + expf(-a_z));
                    float ng = tanhf(a_i + rg * a_h);
                    float h_old = xT[MSG_DIM + j][r];
                    out[(size_t)nid * MEM_DIM + j] = (1.f - zg) * ng + zg * h_old;
                }
            }
        }
    }

    if (tid < ROWS && s_nid[tid] >= 0) {
        out[(size_t)n_nodes * MEM_DIM + s_nid[tid]] = s_ts[tid];
    }
}

// ---------------------------------------------------------------------------
extern "C" void kernel_launch(void* const* d_in, const int* in_sizes, int n_in,
                              void* d_out, int out_size) {
    const int*   node_ids    = (const int*)  d_in[0];
    const float* messages    = (const float*)d_in[1];
    const float* timestamps  = (const float*)d_in[2];
    const float* memory      = (const float*)d_in[3];
    const float* last_update = (const float*)d_in[4];
    const float* W_ih        = (const float*)d_in[5];
    const float* W_hh        = (const float*)d_in[6];
    const float* b_ih        = (const float*)d_in[7];
    const float* b_hh        = (const float*)d_in[8];
    float* out = (float*)d_out;

    const int       n_upd   = in_sizes[0];
    const long long n_nodes = in_sizes[4];
    const long long nmem    = n_nodes * (long long)MEM_DIM;

    prep_kernel<<<(KDIM * JPAD + 255) / 256, 256>>>(W_ih, W_hh, b_ih, b_hh);

    int gru_blocks = (n_upd + ROWS - 1) / ROWS;
    bool merged = (n_nodes <= (long long)MASK_CAP) && (gru_blocks >= 80) &&
                  (nmem < (1LL << 33));

    if (merged) {
        mask_kernel<<<(n_upd + 255) / 256, 256>>>(node_ids, n_upd);
        int copy_blocks = gru_blocks / 8;
        if (copy_blocks > 512) copy_blocks = 512;
        fused_kernel<<<gru_blocks + copy_blocks, NTHREADS>>>(
            node_ids, messages, timestamps, memory, last_update, out,
            n_upd, n_nodes, copy_blocks);
    } else {
        long long n4 = (nmem + 3) >> 2;
        copy_kernel<<<(unsigned)((n4 + 255) / 256), 256>>>(memory, out, nmem);
        long long n4b = (n_nodes + 3) >> 2;
        copy_kernel<<<(unsigned)((n4b + 255) / 256), 256>>>(last_update, out + nmem, n_nodes);
        if (n_upd > 0) {
            fused_kernel<<<gru_blocks, NTHREADS>>>(
                node_ids, messages, timestamps, memory, last_update, out,
                n_upd, n_nodes, 0);
        }
    }
}